// round 9
// baseline (speedup 1.0000x reference)
#include <cuda_runtime.h>
#include <math.h>
#include <stdint.h>

#define B 2048
#define C 50257
#define THREADS 512
#define NBLK (148 * 4)          // persistent: fits 4 blocks/SM on 148 or 152 SMs
#define NWARP (THREADS / 32)
#define S 4                     // segments per row
#define SEG_LEN 12565           // ceil(C / S); last segment = 12562
#define NSEG (B * S)            // 8192 work items

// Per-(row,segment) partials + per-row gather + completion counter
__device__ float g_sum[NSEG];
__device__ float g_l1p[NSEG];
__device__ float g_es[NSEG];
__device__ float g_gather[B];
__device__ unsigned int g_count = 0;   // self-resetting via atomicInc wrap

__device__ __forceinline__ void elem(float x, float& sum, float& l1, float& es) {
    sum += x;
    l1 += fabsf(1.f - fmaxf(x, 0.f));   // == (x>0) ? |1-x| : 1  (exact)
    es += __expf(x);
}

__device__ __forceinline__ float wred(float v) {
    v += __shfl_xor_sync(0xffffffffu, v, 16);
    v += __shfl_xor_sync(0xffffffffu, v, 8);
    v += __shfl_xor_sync(0xffffffffu, v, 4);
    v += __shfl_xor_sync(0xffffffffu, v, 2);
    v += __shfl_xor_sync(0xffffffffu, v, 1);
    return v;
}

__global__ __launch_bounds__(THREADS, 4)
void fused_kernel(const float* __restrict__ out, const int* __restrict__ labels,
                  float* __restrict__ res) {
    const int tid  = threadIdx.x;
    const int wid  = tid >> 5;
    const int lane = tid & 31;

    __shared__ float sh_a[NWARP];
    __shared__ float sh_b[NWARP];
    __shared__ float sh_c[NWARP];

    for (int seg = blockIdx.x; seg < NSEG; seg += NBLK) {
        const int row = seg >> 2;
        const int s   = seg & 3;
        const float* rp = out + (long long)row * C;

        // Segment 0's block also performs the label gather for this row
        if (s == 0 && tid == 0) {
            g_gather[row] = __ldg(rp + __ldg(labels + row));
        }

        const int lo = s * SEG_LEN;
        const int hi = (lo + SEG_LEN < C) ? lo + SEG_LEN : C;
        const float* p = rp + lo;
        const int L = hi - lo;   // >= 12562 always

        float sum0 = 0.f, sum1 = 0.f;
        float l10 = 0.f, l11 = 0.f;
        float es0 = 0.f, es1 = 0.f;

        // Alignment peel to 16B (segment base only 4B-aligned)
        const int mis = (int)(((uintptr_t)p >> 2) & 3);
        const int pre = (4 - mis) & 3;
        if (tid < pre) elem(__ldg(p + tid), sum0, l10, es0);

        const float4* p4 = (const float4*)(p + pre);
        const int n4 = (L - pre) >> 2;
        for (int i = tid; i < n4; i += THREADS) {
            float4 v = __ldg(p4 + i);
            elem(v.x, sum0, l10, es0);
            elem(v.y, sum1, l11, es1);
            elem(v.z, sum0, l10, es0);
            elem(v.w, sum1, l11, es1);
        }
        const int tail_start = pre + (n4 << 2);
        if (tid < L - tail_start) elem(__ldg(p + tail_start + tid), sum0, l10, es0);

        // Shuffle-based block reduction
        float rs = wred(sum0 + sum1);
        float rl = wred(l10 + l11);
        float re = wred(es0 + es1);
        if (lane == 0) { sh_a[wid] = rs; sh_b[wid] = rl; sh_c[wid] = re; }
        __syncthreads();
        if (wid == 0) {
            float a = (lane < NWARP) ? sh_a[lane] : 0.f;
            float b = (lane < NWARP) ? sh_b[lane] : 0.f;
            float c = (lane < NWARP) ? sh_c[lane] : 0.f;
            a = wred(a); b = wred(b); c = wred(c);
            if (lane == 0) {
                g_sum[seg] = a;
                g_l1p[seg] = b;
                g_es[seg]  = c;
            }
        }
        __syncthreads();   // protect shared reuse next segment
    }

    // Completion: last of NBLK blocks combines segments + final reduce
    __shared__ bool s_last;
    if (tid == 0) {
        __threadfence();
        s_last = (atomicInc(&g_count, NBLK - 1) == NBLK - 1);
    }
    __syncthreads();

    if (s_last) {
        float accL1 = 0.f, accCE = 0.f;
        #pragma unroll
        for (int k = 0; k < B / THREADS; k++) {
            const int row = tid + k * THREADS;
            const int base = row << 2;
            const float rowsum = g_sum[base] + g_sum[base + 1] + g_sum[base + 2] + g_sum[base + 3];
            const float l1u    = g_l1p[base] + g_l1p[base + 1] + g_l1p[base + 2] + g_l1p[base + 3];
            const float es     = g_es[base]  + g_es[base + 1]  + g_es[base + 2]  + g_es[base + 3];
            const float g = g_gather[row];

            // remove generic term at label column, add the real one
            const float wrong = fabsf(1.f - fmaxf(g, 0.f));   // unscaled
            const float mean = rowsum * (1.f / (float)C);
            const float row_val = fmaxf(fabsf(mean), fabsf(g)) * 10.f;
            const float temp_out_lbl = (g > 0.f) ? -10.f * g : 0.f;
            const float right = fabsf(temp_out_lbl - row_val);

            accL1 += (l1u - wrong) * 10.f + right;
            accCE += logf(es) - g;
        }

        __shared__ float fa[NWARP];
        __shared__ float fb[NWARP];
        float a = wred(accL1);
        float b = wred(accCE);
        if (lane == 0) { fa[wid] = a; fb[wid] = b; }
        __syncthreads();
        if (wid == 0) {
            float ra = (lane < NWARP) ? fa[lane] : 0.f;
            float rb = (lane < NWARP) ? fb[lane] : 0.f;
            ra = wred(ra); rb = wred(rb);
            if (lane == 0) {
                const float l1_mean = ra / ((float)B * (float)C);
                const float ce_mean = rb / (float)B;
                res[0] = 0.5f * l1_mean + 0.5f * ce_mean;
            }
        }
    }
}

extern "C" void kernel_launch(void* const* d_in, const int* in_sizes, int n_in,
                              void* d_out, int out_size) {
    const float* out = (const float*)d_in[0];
    const int* labels = (const int*)d_in[1];
    float* res = (float*)d_out;

    fused_kernel<<<NBLK, THREADS>>>(out, labels, res);
}

// round 10
// speedup vs baseline: 1.1995x; 1.1995x over previous
#include <cuda_runtime.h>
#include <math.h>
#include <stdint.h>

#define B 2048
#define C 50257
#define THREADS 512
#define NBLK (148 * 4)          // persistent: fits 4 blocks/SM on 148 or 152 SMs
#define NWARP (THREADS / 32)
// Guaranteed in-bounds unrolled region: n4 >= 12563 for every row alignment.
#define FULL_ITERS 12
#define FULL_F4 (FULL_ITERS * 2 * THREADS)

// Per-row partials + completion counter (device globals: allocation-guard-safe)
__device__ float g_l1[B];
__device__ float g_ce[B];
__device__ unsigned int g_count = 0;   // self-resetting via atomicInc wrap

__device__ __forceinline__ void elem(float x, float& sum, float& l1, float& es) {
    sum += x;
    l1 += fabsf(1.f - fmaxf(x, 0.f));   // == (x>0) ? |1-x| : 1  (exact)
    es += __expf(x);
}

__device__ __forceinline__ float wred(float v) {
    v += __shfl_xor_sync(0xffffffffu, v, 16);
    v += __shfl_xor_sync(0xffffffffu, v, 8);
    v += __shfl_xor_sync(0xffffffffu, v, 4);
    v += __shfl_xor_sync(0xffffffffu, v, 2);
    v += __shfl_xor_sync(0xffffffffu, v, 1);
    return v;
}

__global__ __launch_bounds__(THREADS, 4)
void fused_kernel(const float* __restrict__ out, const int* __restrict__ labels,
                  float* __restrict__ res) {
    const int tid  = threadIdx.x;
    const int wid  = tid >> 5;
    const int lane = tid & 31;

    __shared__ float sh_a[NWARP];
    __shared__ float sh_b[NWARP];
    __shared__ float sh_c[NWARP];

    for (int row = blockIdx.x; row < B; row += NBLK) {
        const float* rp = out + (long long)row * C;

        // Prefetch label + gathered logit early (only tid 0 needs them at the end)
        float g = 0.f;
        if (tid == 0) {
            g = __ldg(rp + __ldg(labels + row));
        }

        float sum0 = 0.f, sum1 = 0.f;
        float l10 = 0.f, l11 = 0.f;
        float es0 = 0.f, es1 = 0.f;

        // Alignment peel to 16B (row base only 4B-aligned: C odd)
        const int mis = (int)(((uintptr_t)rp >> 2) & 3);
        const int pre = (4 - mis) & 3;
        if (tid < pre) elem(__ldg(rp + tid), sum0, l10, es0);

        const float4* rp4 = (const float4*)(rp + pre);
        const int n4 = (C - pre) >> 2;

        // Hot region: guaranteed in-bounds, 2 independent streaming LDG.128/iter
        #pragma unroll 1
        for (int it = 0; it < FULL_ITERS; ++it) {
            const int i = it * (2 * THREADS) + tid;
            float4 a = __ldcs(rp4 + i);            // evict-first: read-once stream
            float4 b = __ldcs(rp4 + i + THREADS);
            elem(a.x, sum0, l10, es0);
            elem(a.y, sum1, l11, es1);
            elem(a.z, sum0, l10, es0);
            elem(a.w, sum1, l11, es1);
            elem(b.x, sum0, l10, es0);
            elem(b.y, sum1, l11, es1);
            elem(b.z, sum0, l10, es0);
            elem(b.w, sum1, l11, es1);
        }
        for (int i = FULL_F4 + tid; i < n4; i += THREADS) {
            float4 a = __ldcs(rp4 + i);
            elem(a.x, sum0, l10, es0);
            elem(a.y, sum1, l11, es1);
            elem(a.z, sum0, l10, es0);
            elem(a.w, sum1, l11, es1);
        }
        const int tail_start = pre + (n4 << 2);
        if (tid < C - tail_start) elem(__ldg(rp + tail_start + tid), sum0, l10, es0);

        // Shuffle-based block reduction (1 barrier)
        float s = wred(sum0 + sum1);
        float l = wred(l10 + l11);
        float e = wred(es0 + es1);
        if (lane == 0) { sh_a[wid] = s; sh_b[wid] = l; sh_c[wid] = e; }
        __syncthreads();

        if (wid == 0) {
            float rs = (lane < NWARP) ? sh_a[lane] : 0.f;
            float rl = (lane < NWARP) ? sh_b[lane] : 0.f;
            float re = (lane < NWARP) ? sh_c[lane] : 0.f;
            rs = wred(rs); rl = wred(rl); re = wred(re);

            if (lane == 0) {
                // remove generic term at label column, add the real one
                const float wrong = fabsf(1.f - fmaxf(g, 0.f));   // unscaled
                const float mean = rs * (1.f / (float)C);
                const float row_val = fmaxf(fabsf(mean), fabsf(g)) * 10.f;
                const float temp_out_lbl = (g > 0.f) ? -10.f * g : 0.f;
                const float right = fabsf(temp_out_lbl - row_val);
                g_l1[row] = (rl - wrong) * 10.f + right;
                g_ce[row] = logf(re) - g;
            }
        }
        __syncthreads();   // protect shared reuse next row iteration
    }

    // Completion: last of NBLK blocks does the deterministic final reduce
    __shared__ bool s_last;
    if (tid == 0) {
        __threadfence();
        s_last = (atomicInc(&g_count, NBLK - 1) == NBLK - 1);
    }
    __syncthreads();

    if (s_last) {
        float a = 0.f, b = 0.f;
        #pragma unroll
        for (int k = 0; k < B / THREADS; k++) {
            a += g_l1[tid + k * THREADS];
            b += g_ce[tid + k * THREADS];
        }
        __shared__ float fa[NWARP];
        __shared__ float fb[NWARP];
        a = wred(a);
        b = wred(b);
        if (lane == 0) { fa[wid] = a; fb[wid] = b; }
        __syncthreads();
        if (wid == 0) {
            float ra = (lane < NWARP) ? fa[lane] : 0.f;
            float rb = (lane < NWARP) ? fb[lane] : 0.f;
            ra = wred(ra); rb = wred(rb);
            if (lane == 0) {
                const float l1_mean = ra / ((float)B * (float)C);
                const float ce_mean = rb / (float)B;
                res[0] = 0.5f * l1_mean + 0.5f * ce_mean;
            }
        }
    }
}

extern "C" void kernel_launch(void* const* d_in, const int* in_sizes, int n_in,
                              void* d_out, int out_size) {
    const float* out = (const float*)d_in[0];
    const int* labels = (const int*)d_in[1];
    float* res = (float*)d_out;

    fused_kernel<<<NBLK, THREADS>>>(out, labels, res);
}

// round 11
// speedup vs baseline: 1.2806x; 1.0677x over previous
#include <cuda_runtime.h>
#include <math.h>
#include <stdint.h>

#define B 2048
#define C 50257
#define THREADS 512
#define OCC 3
#define NBLK (148 * OCC)        // persistent, all wave-1 resident at 3 CTAs/SM
#define NWARP (THREADS / 32)
// Guaranteed in-bounds unrolled region: n4 >= 12563 for every row alignment.
// 6 iterations x (4*THREADS) float4 = 12288 <= 12563.
#define FULL_ITERS 6
#define FULL_F4 (FULL_ITERS * 4 * THREADS)

// Per-row partials + completion counter (device globals: allocation-guard-safe)
__device__ float g_l1[B];
__device__ float g_ce[B];
__device__ unsigned int g_count = 0;   // self-resetting via atomicInc wrap

__device__ __forceinline__ void elem(float x, float& sum, float& l1, float& es) {
    sum += x;
    l1 += fabsf(1.f - fmaxf(x, 0.f));   // == (x>0) ? |1-x| : 1  (exact)
    es += __expf(x);
}

__device__ __forceinline__ void elem4(const float4 v, float& s0, float& s1,
                                      float& l0, float& l1, float& e0, float& e1) {
    elem(v.x, s0, l0, e0);
    elem(v.y, s1, l1, e1);
    elem(v.z, s0, l0, e0);
    elem(v.w, s1, l1, e1);
}

__device__ __forceinline__ float wred(float v) {
    v += __shfl_xor_sync(0xffffffffu, v, 16);
    v += __shfl_xor_sync(0xffffffffu, v, 8);
    v += __shfl_xor_sync(0xffffffffu, v, 4);
    v += __shfl_xor_sync(0xffffffffu, v, 2);
    v += __shfl_xor_sync(0xffffffffu, v, 1);
    return v;
}

__global__ __launch_bounds__(THREADS, OCC)
void fused_kernel(const float* __restrict__ out, const int* __restrict__ labels,
                  float* __restrict__ res) {
    const int tid  = threadIdx.x;
    const int wid  = tid >> 5;
    const int lane = tid & 31;

    __shared__ float sh_a[NWARP];
    __shared__ float sh_b[NWARP];
    __shared__ float sh_c[NWARP];

    for (int row = blockIdx.x; row < B; row += NBLK) {
        const float* rp = out + (long long)row * C;

        // Prefetch label + gathered logit early (only tid 0 needs them at the end)
        float g = 0.f;
        if (tid == 0) {
            g = __ldg(rp + __ldg(labels + row));
        }

        float sum0 = 0.f, sum1 = 0.f;
        float l10 = 0.f, l11 = 0.f;
        float es0 = 0.f, es1 = 0.f;

        // Alignment peel to 16B (row base only 4B-aligned: C odd)
        const int mis = (int)(((uintptr_t)rp >> 2) & 3);
        const int pre = (4 - mis) & 3;
        if (tid < pre) elem(__ldg(rp + tid), sum0, l10, es0);

        const float4* rp4 = (const float4*)(rp + pre);
        const int n4 = (C - pre) >> 2;

        // Hot region: 4 independent LDG.128 in flight per thread (2 KB/warp)
        #pragma unroll 1
        for (int it = 0; it < FULL_ITERS; ++it) {
            const int i = it * (4 * THREADS) + tid;
            float4 a = __ldcs(rp4 + i);
            float4 b = __ldcs(rp4 + i + THREADS);
            float4 c = __ldcs(rp4 + i + 2 * THREADS);
            float4 d = __ldcs(rp4 + i + 3 * THREADS);
            elem4(a, sum0, sum1, l10, l11, es0, es1);
            elem4(b, sum0, sum1, l10, l11, es0, es1);
            elem4(c, sum0, sum1, l10, l11, es0, es1);
            elem4(d, sum0, sum1, l10, l11, es0, es1);
        }
        // Remainder float4s (< THREADS of them after the 12288 hot region)
        for (int i = FULL_F4 + tid; i < n4; i += THREADS) {
            float4 a = __ldcs(rp4 + i);
            elem4(a, sum0, sum1, l10, l11, es0, es1);
        }
        // Scalar tail (< 4 elems)
        const int tail_start = pre + (n4 << 2);
        if (tid < C - tail_start) elem(__ldg(rp + tail_start + tid), sum0, l10, es0);

        // Shuffle-based block reduction (1 barrier)
        float s = wred(sum0 + sum1);
        float l = wred(l10 + l11);
        float e = wred(es0 + es1);
        if (lane == 0) { sh_a[wid] = s; sh_b[wid] = l; sh_c[wid] = e; }
        __syncthreads();

        if (wid == 0) {
            float rs = (lane < NWARP) ? sh_a[lane] : 0.f;
            float rl = (lane < NWARP) ? sh_b[lane] : 0.f;
            float re = (lane < NWARP) ? sh_c[lane] : 0.f;
            rs = wred(rs); rl = wred(rl); re = wred(re);

            if (lane == 0) {
                // remove generic term at label column, add the real one
                const float wrong = fabsf(1.f - fmaxf(g, 0.f));   // unscaled
                const float mean = rs * (1.f / (float)C);
                const float row_val = fmaxf(fabsf(mean), fabsf(g)) * 10.f;
                const float temp_out_lbl = (g > 0.f) ? -10.f * g : 0.f;
                const float right = fabsf(temp_out_lbl - row_val);
                g_l1[row] = (rl - wrong) * 10.f + right;
                g_ce[row] = logf(re) - g;
            }
        }
        __syncthreads();   // protect shared reuse next row iteration
    }

    // Completion: last of NBLK blocks does the deterministic final reduce
    __shared__ bool s_last;
    if (tid == 0) {
        __threadfence();
        s_last = (atomicInc(&g_count, NBLK - 1) == NBLK - 1);
    }
    __syncthreads();

    if (s_last) {
        float a = 0.f, b = 0.f;
        #pragma unroll
        for (int k = 0; k < B / THREADS; k++) {
            a += g_l1[tid + k * THREADS];
            b += g_ce[tid + k * THREADS];
        }
        __shared__ float fa[NWARP];
        __shared__ float fb[NWARP];
        a = wred(a);
        b = wred(b);
        if (lane == 0) { fa[wid] = a; fb[wid] = b; }
        __syncthreads();
        if (wid == 0) {
            float ra = (lane < NWARP) ? fa[lane] : 0.f;
            float rb = (lane < NWARP) ? fb[lane] : 0.f;
            ra = wred(ra); rb = wred(rb);
            if (lane == 0) {
                const float l1_mean = ra / ((float)B * (float)C);
                const float ce_mean = rb / (float)B;
                res[0] = 0.5f * l1_mean + 0.5f * ce_mean;
            }
        }
    }
}

extern "C" void kernel_launch(void* const* d_in, const int* in_sizes, int n_in,
                              void* d_out, int out_size) {
    const float* out = (const float*)d_in[0];
    const int* labels = (const int*)d_in[1];
    float* res = (float*)d_out;

    fused_kernel<<<NBLK, THREADS>>>(out, labels, res);
}